// round 1
// baseline (speedup 1.0000x reference)
#include <cuda_runtime.h>
#include <cuda_fp16.h>

#define BB 256
#define SS 2048
#define EE 64
#define HH 128
#define G4 512   // 4*H

// x_proj scratch: [S][B][4H] fp32 = 1.07 GB (device-global scratch is the sanctioned workaround)
__device__ float g_xp[(size_t)SS * BB * G4];

__device__ __forceinline__ float sigm_f(float x) {
    return 1.0f / (1.0f + __expf(-x));
}
__device__ __forceinline__ float tanh_f(float x) {
    // 2*sigmoid(2x)-1 ; saturates correctly at +-1 for large |x|
    return 2.0f / (1.0f + __expf(-2.0f * x)) - 1.0f;
}

// ---------------------------------------------------------------------------
// Kernel 1: x_proj[s][b][f] = dot(inputs[b][s][:], U_all[f][:]) + b_u[f]
// Tiled fp32 GEMM: block tile 64(b) x 64(f) x K=64, grid (8 f, 4 b, 2048 s)
// ---------------------------------------------------------------------------
__global__ __launch_bounds__(256) void xproj_kernel(
    const float* __restrict__ inputs,   // [B][S][E]
    const float* __restrict__ U_all,    // [4H][E]
    const float* __restrict__ b_u)      // [4H]
{
    __shared__ float xT[64 * 68];  // [e][b], pitch 68 (bank rotation 4)
    __shared__ float uT[64 * 68];  // [e][f]

    const int s      = blockIdx.z;
    const int b_base = blockIdx.y * 64;
    const int f_base = blockIdx.x * 64;
    const int tid    = threadIdx.x;
    const int e      = tid & 63;
    const int r0     = tid >> 6;   // 0..3

    #pragma unroll
    for (int i = 0; i < 16; i++) {
        int r = r0 + i * 4;
        xT[e * 68 + r] = inputs[((size_t)(b_base + r) * SS + s) * EE + e];
        uT[e * 68 + r] = U_all[(size_t)(f_base + r) * EE + e];
    }
    __syncthreads();

    const int bi = (tid >> 4) * 4;   // batch sub-tile 0..60
    const int fi = (tid & 15) * 4;   // f sub-tile 0..60

    float acc[4][4];
    #pragma unroll
    for (int i = 0; i < 4; i++)
        #pragma unroll
        for (int j = 0; j < 4; j++) acc[i][j] = 0.0f;

    #pragma unroll 16
    for (int k = 0; k < 64; k++) {
        float4 xv = *reinterpret_cast<const float4*>(&xT[k * 68 + bi]);
        float4 uv = *reinterpret_cast<const float4*>(&uT[k * 68 + fi]);
        float xa[4] = {xv.x, xv.y, xv.z, xv.w};
        float ua[4] = {uv.x, uv.y, uv.z, uv.w};
        #pragma unroll
        for (int i = 0; i < 4; i++)
            #pragma unroll
            for (int j = 0; j < 4; j++)
                acc[i][j] += xa[i] * ua[j];
    }

    float4 bu = *reinterpret_cast<const float4*>(&b_u[f_base + fi]);
    #pragma unroll
    for (int i = 0; i < 4; i++) {
        size_t o = ((size_t)s * BB + (size_t)(b_base + bi + i)) * G4 + f_base + fi;
        float4 v;
        v.x = acc[i][0] + bu.x;
        v.y = acc[i][1] + bu.y;
        v.z = acc[i][2] + bu.z;
        v.w = acc[i][3] + bu.w;
        *reinterpret_cast<float4*>(&g_xp[o]) = v;
    }
}

// ---------------------------------------------------------------------------
// Kernel 2: the sequential scan. 128 CTAs x 512 threads, 2 batch rows per CTA.
// Weights fp16-resident in SMEM; h,c fp32 in SMEM; 2 syncthreads per step.
//   Phase A: thread t computes gate preacts n=t for m=0,1 (K=128) plus a
//            half-K partial of the W_d dot (balanced across all 512 threads).
//   Phase B: threads 0..255 do the gating math for (m,j), update h,c, and
//            accumulate out += h_new * W_out[j].
// ---------------------------------------------------------------------------
#define WPITCH 136                       // fp16 row pitch: 272B, bank rot 4
#define SM_WALL   0                      // 512*136 halves  = 139264 B
#define SM_WD     139264                 // 128*136 halves  =  34816 B
#define SM_H      174080                 // 2*128 floats    =   1024 B
#define SM_C      175104                 // 2*128 floats    =   1024 B
#define SM_PRE    176128                 // 2*512 floats    =   4096 B
#define SM_CPART  180224                 // 2*2*128 floats  =   2048 B
#define SMEM_BYTES 182272

__global__ __launch_bounds__(512, 1) void scan_kernel(
    const float* __restrict__ TI,      // [B][S]
    const float* __restrict__ W_all,   // [4H][H]
    const float* __restrict__ b_all,   // [4H]
    const float* __restrict__ W_d,     // [H][H]
    const float* __restrict__ b_d,     // [H]
    const float* __restrict__ W_out,   // [1][H]
    const float* __restrict__ b_out,   // [1]
    float* __restrict__ out)           // [B]
{
    extern __shared__ char smem[];
    __half* wall  = reinterpret_cast<__half*>(smem + SM_WALL);
    __half* wd    = reinterpret_cast<__half*>(smem + SM_WD);
    float*  hbuf  = reinterpret_cast<float*>(smem + SM_H);
    float*  cbuf  = reinterpret_cast<float*>(smem + SM_C);
    float*  pre   = reinterpret_cast<float*>(smem + SM_PRE);
    float*  cpart = reinterpret_cast<float*>(smem + SM_CPART);

    const int t  = threadIdx.x;
    const int b0 = blockIdx.x * 2;

    // One-time: fp32 -> fp16 weight conversion into padded SMEM rows
    for (int idx = t; idx < G4 * HH; idx += 512)
        wall[(idx >> 7) * WPITCH + (idx & 127)] = __float2half_rn(W_all[idx]);
    for (int idx = t; idx < HH * HH; idx += 512)
        wd[(idx >> 7) * WPITCH + (idx & 127)] = __float2half_rn(W_d[idx]);
    if (t < 256) { hbuf[t] = 0.0f; cbuf[t] = 0.0f; }

    const float ba = b_all[t];

    // W_d half-dot assignment: (khalf, m2, j) covers {0,1}x{0,1}x[0,128)
    const int j     = t & 127;
    const int m2    = (t >> 7) & 1;
    const int khalf = t >> 8;

    float bd_r = 0.0f, wout_r = 0.0f;
    if (t < 256) { bd_r = b_d[j]; wout_r = W_out[j]; }
    const float bo = b_out[0];

    __syncthreads();

    const uint4*  wrow  = reinterpret_cast<const uint4*>(wall + t * WPITCH);           // 16 x 8 halves
    const uint4*  wdrow = reinterpret_cast<const uint4*>(wd + j * WPITCH) + khalf * 8; // 8 x 8 halves
    const float4* h0v   = reinterpret_cast<const float4*>(hbuf);
    const float4* h1v   = reinterpret_cast<const float4*>(hbuf + 128);
    const float4* cv    = reinterpret_cast<const float4*>(cbuf + m2 * 128) + khalf * 16;

    float out_acc = 0.0f;

    for (int s = 0; s < SS; s++) {
        // ---- Phase A: GEMMs ----
        size_t xb = ((size_t)s * BB + b0) * G4 + t;
        float xp0 = g_xp[xb];
        float xp1 = g_xp[xb + G4];

        float a0 = 0.0f, a1 = 0.0f;
        #pragma unroll
        for (int kc = 0; kc < 16; kc++) {
            uint4 wv = wrow[kc];
            float2 w0 = __half22float2(*reinterpret_cast<const __half2*>(&wv.x));
            float2 w1 = __half22float2(*reinterpret_cast<const __half2*>(&wv.y));
            float2 w2 = __half22float2(*reinterpret_cast<const __half2*>(&wv.z));
            float2 w3 = __half22float2(*reinterpret_cast<const __half2*>(&wv.w));
            float4 p0 = h0v[2 * kc], p1 = h0v[2 * kc + 1];
            float4 q0 = h1v[2 * kc], q1 = h1v[2 * kc + 1];
            a0 += p0.x * w0.x; a0 += p0.y * w0.y; a0 += p0.z * w1.x; a0 += p0.w * w1.y;
            a0 += p1.x * w2.x; a0 += p1.y * w2.y; a0 += p1.z * w3.x; a0 += p1.w * w3.y;
            a1 += q0.x * w0.x; a1 += q0.y * w0.y; a1 += q0.z * w1.x; a1 += q0.w * w1.y;
            a1 += q1.x * w2.x; a1 += q1.y * w2.y; a1 += q1.z * w3.x; a1 += q1.w * w3.y;
        }

        float aw = 0.0f;
        #pragma unroll
        for (int kc = 0; kc < 8; kc++) {
            uint4 wv = wdrow[kc];
            float2 w0 = __half22float2(*reinterpret_cast<const __half2*>(&wv.x));
            float2 w1 = __half22float2(*reinterpret_cast<const __half2*>(&wv.y));
            float2 w2 = __half22float2(*reinterpret_cast<const __half2*>(&wv.z));
            float2 w3 = __half22float2(*reinterpret_cast<const __half2*>(&wv.w));
            float4 p0 = cv[2 * kc], p1 = cv[2 * kc + 1];
            aw += p0.x * w0.x; aw += p0.y * w0.y; aw += p0.z * w1.x; aw += p0.w * w1.y;
            aw += p1.x * w2.x; aw += p1.y * w2.y; aw += p1.z * w3.x; aw += p1.w * w3.y;
        }

        pre[t]       = a0 + ba + xp0;
        pre[512 + t] = a1 + ba + xp1;
        cpart[(khalf * 2 + m2) * 128 + j] = aw;
        __syncthreads();

        // ---- Phase B: gating (threads 0..255; (m, j) = (t>>7, t&127)) ----
        if (t < 256) {
            const int m  = t >> 7;
            const int jb = t & 127;
            float fg = sigm_f(pre[m * 512 + jb]);
            float ig = sigm_f(pre[m * 512 + 128 + jb]);
            float og = sigm_f(pre[m * 512 + 256 + jb]);
            float ct = sigm_f(pre[m * 512 + 384 + jb]);
            float cp = cpart[m * 128 + jb] + cpart[(2 + m) * 128 + jb] + bd_r;
            float cs1 = tanh_f(cp);
            float d   = TI[(size_t)(b0 + m) * SS + s];
            float cold = cbuf[m * 128 + jb];
            float cadj = (cold - cs1) + cs1 * d;
            float cnew = fg * cadj + ig * ct;
            float hnew = og * tanh_f(cnew);
            cbuf[m * 128 + jb] = cnew;
            hbuf[m * 128 + jb] = hnew;
            out_acc += hnew * wout_r;
        }
        __syncthreads();
    }

    // ---- Output reduction: out[b] = sum_s h_s @ W_out + S * b_out ----
    if (t < 256) pre[t] = out_acc;
    __syncthreads();
    if (t == 0) {
        float s0 = 0.0f;
        for (int k = 0; k < 128; k++) s0 += pre[k];
        out[b0] = s0 + (float)SS * bo;
    }
    if (t == 1) {
        float s1 = 0.0f;
        for (int k = 0; k < 128; k++) s1 += pre[128 + k];
        out[b0 + 1] = s1 + (float)SS * bo;
    }
}

// ---------------------------------------------------------------------------
extern "C" void kernel_launch(void* const* d_in, const int* in_sizes, int n_in,
                              void* d_out, int out_size)
{
    const float* inputs = (const float*)d_in[0];
    const float* TI     = (const float*)d_in[1];
    const float* W_all  = (const float*)d_in[2];
    const float* b_all  = (const float*)d_in[3];
    const float* U_all  = (const float*)d_in[4];
    const float* b_u    = (const float*)d_in[5];
    const float* W_d    = (const float*)d_in[6];
    const float* b_d    = (const float*)d_in[7];
    const float* W_out  = (const float*)d_in[8];
    const float* b_out  = (const float*)d_in[9];
    float* out = (float*)d_out;

    xproj_kernel<<<dim3(8, 4, SS), 256>>>(inputs, U_all, b_u);

    cudaFuncSetAttribute(scan_kernel,
                         cudaFuncAttributeMaxDynamicSharedMemorySize, SMEM_BYTES);
    scan_kernel<<<128, 512, SMEM_BYTES>>>(TI, W_all, b_all, W_d, b_d,
                                          W_out, b_out, out);
}